// round 2
// baseline (speedup 1.0000x reference)
#include <cuda_runtime.h>
#include <math.h>

#define H 1024
#define V 50257
#define S 4096

// ---------------- scratch (__device__ globals, no allocation) ----------------
__device__ float g_gi[3 * H];
__device__ float g_gh[3 * H];
__device__ float g_h[H];
__device__ float g_vpart[16][H];
__device__ float g_v[H];
__device__ float g_scores[S];
__device__ float g_w[S];
__device__ float g_ctxpart[32][H];
__device__ float g_ctx[H];
__device__ float g_logh[V];        // h-part of logits (computed on side stream)

// ---------------- helpers ----------------
__device__ __forceinline__ float warp_sum(float v) {
#pragma unroll
    for (int o = 16; o; o >>= 1) v += __shfl_xor_sync(0xffffffffu, v, o);
    return v;
}

// ---------------- K1: gates  gi = w_ih @ x + b_ih ; gh = w_hh @ h_prev + b_hh
__global__ void k_gates(const int* __restrict__ word,
                        const float* __restrict__ last_hidden,
                        const float* __restrict__ emb,
                        const float* __restrict__ w_ih,
                        const float* __restrict__ w_hh,
                        const float* __restrict__ b_ih,
                        const float* __restrict__ b_hh) {
    int b = blockIdx.x;
    const float* W;
    const float* vec;
    float bias;
    float* out;
    if (b < 3 * H) {
        int row = b;
        W = w_ih + (long)row * H;
        vec = emb + (long)word[0] * H;
        bias = b_ih[row];
        out = &g_gi[row];
    } else {
        int row = b - 3 * H;
        W = w_hh + (long)row * H;
        vec = last_hidden;
        bias = b_hh[row];
        out = &g_gh[row];
    }
    int t = threadIdx.x;
    float4 a = reinterpret_cast<const float4*>(W)[t];
    float4 x = reinterpret_cast<const float4*>(vec)[t];
    float s = a.x * x.x + a.y * x.y + a.z * x.z + a.w * x.w;

    s = warp_sum(s);
    __shared__ float sm[8];
    int w = t >> 5, l = t & 31;
    if (!l) sm[w] = s;
    __syncthreads();
    if (w == 0) {
        s = (l < 8) ? sm[l] : 0.f;
#pragma unroll
        for (int o = 4; o; o >>= 1) s += __shfl_xor_sync(0xffffffffu, s, o);
        if (!l) *out = s + bias;
    }
}

// ---------------- K2: GRU combine. 1 block x 1024.
__global__ void k_gru(const float* __restrict__ last_hidden, float* __restrict__ dout) {
    int i = threadIdx.x;
    float hp = last_hidden[i];
    float r = 1.f / (1.f + expf(-(g_gi[i] + g_gh[i])));
    float z = 1.f / (1.f + expf(-(g_gi[H + i] + g_gh[H + i])));
    float n = tanhf(g_gi[2 * H + i] + r * g_gh[2 * H + i]);
    float h = (1.f - z) * n + z * hp;
    g_h[i] = h;
    dout[V + i] = h;
}

// ---------------- side stream: logits h-part: g_logh[r] = h . out_w[r][0:H]
__global__ void k_logits_h(const float* __restrict__ out_w) {
    __shared__ float4 hv[256];
    int t = threadIdx.x;
    hv[t] = reinterpret_cast<const float4*>(g_h)[t];
    __syncthreads();
    int warp = t >> 5, lane = t & 31;
    int r = blockIdx.x * 8 + warp;
    if (r >= V) return;
    const float4* wr = reinterpret_cast<const float4*>(out_w + (long)r * (2 * H));
    float acc = 0.f;
#pragma unroll
    for (int it = 0; it < 8; it++) {
        float4 w = wr[it * 32 + lane];
        float4 c = hv[it * 32 + lane];
        acc += w.x * c.x + w.y * c.y + w.z * c.z + w.w * c.w;
    }
    acc = warp_sum(acc);
    if (!lane) g_logh[r] = acc;
}

// ---------------- K3: v partials: v[c] = sum_j attn_w[j][c] * h[j]
__global__ void k_vpart(const float* __restrict__ attn_w) {
    int c = blockIdx.x * 256 + threadIdx.x;
    int jc = blockIdx.y;
    float s = 0.f;
    const float* base = attn_w + (long)(jc * 64) * H + c;
#pragma unroll 8
    for (int j = 0; j < 64; j++)
        s += base[(long)j * H] * g_h[jc * 64 + j];
    g_vpart[jc][c] = s;
}

// ---------------- K4: reduce v partials.
__global__ void k_vred() {
    int c = threadIdx.x;
    float s = 0.f;
#pragma unroll
    for (int j = 0; j < 16; j++) s += g_vpart[j][c];
    g_v[c] = s;
}

// ---------------- K5: scores[s] = enc[s] . v   (attn_b is a softmax-invariant shift)
__global__ void k_scores(const float* __restrict__ enc) {
    int warp = threadIdx.x >> 5, lane = threadIdx.x & 31;
    int s = blockIdx.x * 8 + warp;
    const float4* er = reinterpret_cast<const float4*>(enc + (long)s * H);
    const float4* vr = reinterpret_cast<const float4*>(g_v);
    float acc = 0.f;
#pragma unroll
    for (int it = 0; it < 8; it++) {
        float4 e = er[it * 32 + lane];
        float4 v = vr[it * 32 + lane];
        acc += e.x * v.x + e.y * v.y + e.z * v.z + e.w * v.w;
    }
    acc = warp_sum(acc);
    if (!lane) g_scores[s] = acc;
}

// ---------------- K6: softmax over 4096 scores, writes attn_weights output.
__global__ void k_softmax(float* __restrict__ dout) {
    __shared__ float sm[32];
    __shared__ float bc;
    int t = threadIdx.x, w = t >> 5, l = t & 31;
    float x[4];
    float m = -INFINITY;
#pragma unroll
    for (int k = 0; k < 4; k++) {
        x[k] = g_scores[t * 4 + k];
        m = fmaxf(m, x[k]);
    }
#pragma unroll
    for (int o = 16; o; o >>= 1) m = fmaxf(m, __shfl_xor_sync(0xffffffffu, m, o));
    if (!l) sm[w] = m;
    __syncthreads();
    if (w == 0) {
        m = sm[l];
#pragma unroll
        for (int o = 16; o; o >>= 1) m = fmaxf(m, __shfl_xor_sync(0xffffffffu, m, o));
        if (!l) bc = m;
    }
    __syncthreads();
    m = bc;
    float e[4];
    float sum = 0.f;
#pragma unroll
    for (int k = 0; k < 4; k++) {
        e[k] = expf(x[k] - m);
        sum += e[k];
    }
    sum = warp_sum(sum);
    __syncthreads();
    if (!l) sm[w] = sum;
    __syncthreads();
    if (w == 0) {
        sum = sm[l];
        sum = warp_sum(sum);
        if (!l) bc = sum;
    }
    __syncthreads();
    float inv = 1.f / bc;
#pragma unroll
    for (int k = 0; k < 4; k++) {
        float wt = e[k] * inv;
        g_w[t * 4 + k] = wt;
        dout[V + H + t * 4 + k] = wt;
    }
}

// ---------------- K7: context partials
__global__ void k_ctxpart(const float* __restrict__ enc) {
    int c = blockIdx.x * 256 + threadIdx.x;
    int sc = blockIdx.y;
    float acc = 0.f;
    const float* base = enc + (long)(sc * 128) * H + c;
#pragma unroll 8
    for (int s = 0; s < 128; s++)
        acc += g_w[sc * 128 + s] * base[(long)s * H];
    g_ctxpart[sc][c] = acc;
}

// ---------------- K8: reduce context partials.
__global__ void k_ctxred() {
    int c = threadIdx.x;
    float s = 0.f;
#pragma unroll
    for (int j = 0; j < 32; j++) s += g_ctxpart[j][c];
    g_ctx[c] = s;
}

// ---------------- K9 (join): dout[r] = g_logh[r] + ctx . out_w[r][H:2H] + out_b[r]
__global__ void k_logits_ctx(const float* __restrict__ out_w,
                             const float* __restrict__ out_b,
                             float* __restrict__ dout) {
    __shared__ float4 cv[256];
    int t = threadIdx.x;
    cv[t] = reinterpret_cast<const float4*>(g_ctx)[t];
    __syncthreads();
    int warp = t >> 5, lane = t & 31;
    int r = blockIdx.x * 8 + warp;
    if (r >= V) return;
    const float4* wr = reinterpret_cast<const float4*>(out_w + (long)r * (2 * H) + H);
    float acc = 0.f;
#pragma unroll
    for (int it = 0; it < 8; it++) {
        float4 w = wr[it * 32 + lane];
        float4 c = cv[it * 32 + lane];
        acc += w.x * c.x + w.y * c.y + w.z * c.z + w.w * c.w;
    }
    acc = warp_sum(acc);
    if (!lane) dout[r] = g_logh[r] + acc + out_b[r];
}

// ---------------- launch (fork/join graph: logits_h overlaps attention chain) ----
extern "C" void kernel_launch(void* const* d_in, const int* in_sizes, int n_in,
                              void* d_out, int out_size) {
    const int* word = (const int*)d_in[0];
    const float* last_hidden = (const float*)d_in[1];
    const float* enc = (const float*)d_in[2];
    const float* emb = (const float*)d_in[3];
    const float* w_ih = (const float*)d_in[4];
    const float* w_hh = (const float*)d_in[5];
    const float* b_ih = (const float*)d_in[6];
    const float* b_hh = (const float*)d_in[7];
    const float* attn_w = (const float*)d_in[8];
    // d_in[9] = attn_b : constant pre-softmax shift -> no-op
    const float* out_w = (const float*)d_in[10];
    const float* out_b = (const float*)d_in[11];
    float* dout = (float*)d_out;

    // Lazily created side stream + events (not device memory; created ~3x total,
    // graph replays never re-enter this function).
    static cudaStream_t s1 = nullptr;
    static cudaEvent_t e_fork = nullptr, e_join = nullptr;
    if (!s1) {
        cudaStreamCreateWithFlags(&s1, cudaStreamNonBlocking);
        cudaEventCreateWithFlags(&e_fork, cudaEventDisableTiming);
        cudaEventCreateWithFlags(&e_join, cudaEventDisableTiming);
    }

    // serial head
    k_gates<<<6 * H, 256>>>(word, last_hidden, emb, w_ih, w_hh, b_ih, b_hh);
    k_gru<<<1, 1024>>>(last_hidden, dout);

    // fork: h-half of the big GEMV (206 MB) runs concurrently with attention chain
    cudaEventRecord(e_fork, 0);
    cudaStreamWaitEvent(s1, e_fork, 0);
    k_logits_h<<<(V + 7) / 8, 256, 0, s1>>>(out_w);
    cudaEventRecord(e_join, s1);

    // attention chain on main stream (hidden under k_logits_h)
    k_vpart<<<dim3(4, 16), 256>>>(attn_w);
    k_vred<<<1, 1024>>>();
    k_scores<<<S / 8, 256>>>(enc);
    k_softmax<<<1, 1024>>>(dout);
    k_ctxpart<<<dim3(4, 32), 256>>>(enc);
    k_ctxred<<<1, 1024>>>();

    // join + ctx-half of the big GEMV (206 MB)
    cudaStreamWaitEvent(0, e_join, 0);
    k_logits_ctx<<<(V + 7) / 8, 256>>>(out_w, out_b, dout);
}

// round 3
// speedup vs baseline: 1.0266x; 1.0266x over previous
#include <cuda_runtime.h>
#include <math.h>

#define H 1024
#define V 50257
#define S 4096
#define NB 296
#define NT 256
#define NWARP (NB * (NT / 32))   // 2368 warps

// ---------------- scratch (__device__ globals) ----------------
__device__ float g_gi[3 * H];
__device__ float g_gh[3 * H];
__device__ float g_h[H];
__device__ float g_vpart[32][H];
__device__ float g_v[H];
__device__ float g_scores[S];
__device__ float g_w[S];
__device__ float g_ctxpart[32][H];
__device__ float g_ctx[H];
__device__ unsigned g_cnt = 0;
__device__ unsigned g_gen = 0;

// ---------------- helpers ----------------
__device__ __forceinline__ float warp_sum(float v) {
#pragma unroll
    for (int o = 16; o; o >>= 1) v += __shfl_xor_sync(0xffffffffu, v, o);
    return v;
}

// software grid barrier: atomic arrival, volatile-poll release (generation flag).
// All NB blocks are co-resident (2/SM), so no deadlock.
__device__ __forceinline__ void grid_sync() {
    __syncthreads();
    if (threadIdx.x == 0) {
        __threadfence();                                   // publish this block's writes
        unsigned gen = *(volatile unsigned*)&g_gen;
        if (atomicAdd(&g_cnt, 1u) == NB - 1) {             // last to arrive
            g_cnt = 0;
            __threadfence();
            *(volatile unsigned*)&g_gen = gen + 1;         // release
        } else {
            while (*(volatile unsigned*)&g_gen == gen) { } // spin on L2
        }
        __threadfence();                                   // acquire
    }
    __syncthreads();
}

// ---------------- the whole model in one persistent kernel ----------------
__global__ void __launch_bounds__(NT, 2)
k_all(const int* __restrict__ word,
      const float* __restrict__ last_hidden,
      const float* __restrict__ enc,
      const float* __restrict__ emb,
      const float* __restrict__ w_ih,
      const float* __restrict__ w_hh,
      const float* __restrict__ b_ih,
      const float* __restrict__ b_hh,
      const float* __restrict__ attn_w,
      const float* __restrict__ out_w,
      const float* __restrict__ out_b,
      float* __restrict__ dout) {
    __shared__ float4 sbuf4[512];          // 8KB, reused per phase
    float* sbuf = (float*)sbuf4;

    const int t = threadIdx.x;
    const int b = blockIdx.x;
    const int warp = t >> 5, lane = t & 31;
    const int gw = b * (NT / 32) + warp;   // global warp id

    // ============ Phase A: gates  gi = w_ih@x + b_ih ; gh = w_hh@h_prev + b_hh
    {
        const float* x = emb + (long)word[0] * H;
        sbuf4[t]       = reinterpret_cast<const float4*>(x)[t];           // x
        sbuf4[256 + t] = reinterpret_cast<const float4*>(last_hidden)[t]; // h_prev
        __syncthreads();
        for (int r = gw; r < 6 * H; r += NWARP) {
            const float* W;
            const float4* vec4;
            float bias;
            float* out;
            if (r < 3 * H) {
                W = w_ih + (long)r * H; vec4 = sbuf4;       bias = b_ih[r]; out = &g_gi[r];
            } else {
                int rr = r - 3 * H;
                W = w_hh + (long)rr * H; vec4 = sbuf4 + 256; bias = b_hh[rr]; out = &g_gh[rr];
            }
            const float4* w4 = reinterpret_cast<const float4*>(W);
            float acc = 0.f;
#pragma unroll
            for (int it = 0; it < 8; it++) {
                float4 a = w4[it * 32 + lane];
                float4 v = vec4[it * 32 + lane];
                acc += a.x * v.x + a.y * v.y + a.z * v.z + a.w * v.w;
            }
            acc = warp_sum(acc);
            if (!lane) *out = acc + bias;
        }
    }
    grid_sync();

    // ============ Phase B: GRU combine (blocks 0..3)
    if (b < 4) {
        int i = b * NT + t;
        float hp = last_hidden[i];
        float r = 1.f / (1.f + expf(-(g_gi[i] + g_gh[i])));
        float z = 1.f / (1.f + expf(-(g_gi[H + i] + g_gh[H + i])));
        float n = tanhf(g_gi[2 * H + i] + r * g_gh[2 * H + i]);
        float h = (1.f - z) * n + z * hp;
        g_h[i] = h;
        dout[V + i] = h;                      // hidden output
    }
    grid_sync();

    // ============ Phase C: v partials  v[c] = sum_j attn_w[j][c]*h[j]  (blocks 0..127)
    if (b < 128) {
        int jc = b >> 2;                      // 32 chunks of 32 rows
        int c = (b & 3) * NT + t;
        const float* base = attn_w + (long)(jc * 32) * H + c;
        float s = 0.f;
#pragma unroll 8
        for (int j = 0; j < 32; j++)
            s += base[(long)j * H] * g_h[jc * 32 + j];
        g_vpart[jc][c] = s;
    }
    grid_sync();

    // ============ Phase D: reduce v partials (blocks 0..3)
    if (b < 4) {
        int c = b * NT + t;
        float s = 0.f;
#pragma unroll
        for (int j = 0; j < 32; j++) s += g_vpart[j][c];
        g_v[c] = s;
    }
    grid_sync();

    // ============ Phase E: scores[s] = enc[s] . v   (attn_b is softmax-invariant)
    {
        sbuf4[t] = reinterpret_cast<const float4*>(g_v)[t];   // v into shared (4KB)
        __syncthreads();
        for (int s = gw; s < S; s += NWARP) {
            const float4* er = reinterpret_cast<const float4*>(enc + (long)s * H);
            float acc = 0.f;
#pragma unroll
            for (int it = 0; it < 8; it++) {
                float4 e = er[it * 32 + lane];
                float4 v = sbuf4[it * 32 + lane];
                acc += e.x * v.x + e.y * v.y + e.z * v.z + e.w * v.w;
            }
            acc = warp_sum(acc);
            if (!lane) g_scores[s] = acc;
        }
    }
    grid_sync();

    // ============ Phase F: softmax over 4096 (block 0), writes attn_weights out
    if (b == 0) {
        float x[16];
        float m = -INFINITY;
#pragma unroll
        for (int k = 0; k < 16; k++) {
            x[k] = g_scores[t + NT * k];
            m = fmaxf(m, x[k]);
        }
#pragma unroll
        for (int o = 16; o; o >>= 1) m = fmaxf(m, __shfl_xor_sync(0xffffffffu, m, o));
        if (!lane) sbuf[warp] = m;
        __syncthreads();
        if (warp == 0) {
            m = (lane < 8) ? sbuf[lane] : -INFINITY;
#pragma unroll
            for (int o = 4; o; o >>= 1) m = fmaxf(m, __shfl_xor_sync(0xffffffffu, m, o));
            if (!lane) sbuf[64] = m;
        }
        __syncthreads();
        m = sbuf[64];
        float e[16];
        float sum = 0.f;
#pragma unroll
        for (int k = 0; k < 16; k++) { e[k] = expf(x[k] - m); sum += e[k]; }
        sum = warp_sum(sum);
        __syncthreads();
        if (!lane) sbuf[warp] = sum;
        __syncthreads();
        if (warp == 0) {
            sum = (lane < 8) ? sbuf[lane] : 0.f;
#pragma unroll
            for (int o = 4; o; o >>= 1) sum += __shfl_xor_sync(0xffffffffu, sum, o);
            if (!lane) sbuf[64] = sum;
        }
        __syncthreads();
        float inv = 1.f / sbuf[64];
#pragma unroll
        for (int k = 0; k < 16; k++) {
            float wt = e[k] * inv;
            g_w[t + NT * k] = wt;
            dout[V + H + t + NT * k] = wt;   // attn_weights output
        }
        __syncthreads();
    }
    grid_sync();

    // ============ Phase G: ctx partials  ctx[c] = sum_s w[s]*enc[s][c]  (blocks 0..127)
    if (b < 128) {
        int sc = b >> 2;                      // 32 chunks of 128 rows
        int c = (b & 3) * NT + t;
        const float* base = enc + (long)(sc * 128) * H + c;
        float acc = 0.f;
#pragma unroll 8
        for (int s = 0; s < 128; s++)
            acc += g_w[sc * 128 + s] * base[(long)s * H];
        g_ctxpart[sc][c] = acc;
    }
    grid_sync();

    // ============ Phase H: reduce ctx partials (blocks 0..3)
    if (b < 4) {
        int c = b * NT + t;
        float s = 0.f;
#pragma unroll
        for (int j = 0; j < 32; j++) s += g_ctxpart[j][c];
        g_ctx[c] = s;
    }
    grid_sync();

    // ============ Phase I: logits[r] = [h;ctx] . out_w[r] + out_b[r]  (412MB stream)
    {
        __syncthreads();
        sbuf4[t]       = reinterpret_cast<const float4*>(g_h)[t];
        sbuf4[256 + t] = reinterpret_cast<const float4*>(g_ctx)[t];
        __syncthreads();
        for (int r = gw; r < V; r += NWARP) {
            const float4* wr = reinterpret_cast<const float4*>(out_w + (long)r * (2 * H));
            float acc = 0.f;
#pragma unroll
            for (int it = 0; it < 16; it++) {
                float4 w = wr[it * 32 + lane];
                float4 c = sbuf4[it * 32 + lane];
                acc += w.x * c.x + w.y * c.y + w.z * c.z + w.w * c.w;
            }
            acc = warp_sum(acc);
            if (!lane) dout[r] = acc + out_b[r];
        }
    }
}

// ---------------- launch ----------------
extern "C" void kernel_launch(void* const* d_in, const int* in_sizes, int n_in,
                              void* d_out, int out_size) {
    const int* word = (const int*)d_in[0];
    const float* last_hidden = (const float*)d_in[1];
    const float* enc = (const float*)d_in[2];
    const float* emb = (const float*)d_in[3];
    const float* w_ih = (const float*)d_in[4];
    const float* w_hh = (const float*)d_in[5];
    const float* b_ih = (const float*)d_in[6];
    const float* b_hh = (const float*)d_in[7];
    const float* attn_w = (const float*)d_in[8];
    // d_in[9] = attn_b : constant pre-softmax shift -> softmax-invariant, dropped
    const float* out_w = (const float*)d_in[10];
    const float* out_b = (const float*)d_in[11];
    float* dout = (float*)d_out;

    k_all<<<NB, NT>>>(word, last_hidden, enc, emb, w_ih, w_hh, b_ih, b_hh,
                      attn_w, out_w, out_b, dout);
}